// round 9
// baseline (speedup 1.0000x reference)
#include <cuda_runtime.h>
#include <math.h>
#include <stdint.h>

#define FULL 0xFFFFFFFFu

// monotone float->u32 key, branchless
__device__ __forceinline__ unsigned f2key(float f) {
    unsigned b = __float_as_uint(f);
    return b ^ (0x80000000u | (unsigned)((int)b >> 31));
}
__device__ __forceinline__ float key2f(unsigned k) {
    unsigned b = (k & 0x80000000u) ? (k ^ 0x80000000u) : ~k;
    return __uint_as_float(b);
}

// comparator on s[tok][]
#define CE2(tok, i, j) { unsigned a_ = s[tok][i], b_ = s[tok][j]; \
                         s[tok][i] = umax(a_, b_); s[tok][j] = umin(a_, b_); }
#define SORT8(tok) \
    CE2(tok,0,1) CE2(tok,2,3) CE2(tok,4,5) CE2(tok,6,7) \
    CE2(tok,0,2) CE2(tok,1,3) CE2(tok,4,6) CE2(tok,5,7) \
    CE2(tok,1,2) CE2(tok,5,6) \
    CE2(tok,0,4) CE2(tok,1,5) CE2(tok,2,6) CE2(tok,3,7) \
    CE2(tok,2,4) CE2(tok,3,5) \
    CE2(tok,1,2) CE2(tok,3,4) CE2(tok,5,6)

__global__ __launch_bounds__(128, 8)   // cap 64 regs; 2 independent chains per warp
void topk_route_kernel(const float* __restrict__ logits,
                       const float* __restrict__ bias,
                       float* __restrict__ out, int T)
{
    const int lane = threadIdx.x & 31;
    const int warp = threadIdx.x >> 5;
    const int tA = (blockIdx.x * 4 + warp) * 2;   // two interleaved tokens
    if (tA >= T) return;
    const bool hasB = (tA + 1) < T;

    const unsigned lmlt = (1u << lane) - 1u;

    // bias once (shared by both tokens)
    const float4* bp = (const float4*)(bias + lane * 8);
    float4 b0 = __ldg(bp), b1 = __ldg(bp + 1);
    float bb[8] = {b0.x, b0.y, b0.z, b0.w, b1.x, b1.y, b1.z, b1.w};

    // all logits loads up front (lane l owns experts [8l,8l+8), group l>>2)
    const float* lgA = logits + (size_t)tA * 256 + lane * 8;
    float4 a0 = *(const float4*)lgA;
    float4 a1 = *(const float4*)(lgA + 4);
    float4 c0 = make_float4(0,0,0,0), c1 = make_float4(0,0,0,0);
    if (hasB) { c0 = *(const float4*)(lgA + 256); c1 = *(const float4*)(lgA + 260); }

    // passthrough both tokens
    float* loA = out + (size_t)T * 16 + (size_t)tA * 256 + lane * 8;
    *(float4*)loA = a0;
    *(float4*)(loA + 4) = a1;
    if (hasB) { *(float4*)(loA + 256) = c0; *(float4*)(loA + 260) = c1; }

    float xx[2][8] = {{a0.x,a0.y,a0.z,a0.w,a1.x,a1.y,a1.z,a1.w},
                      {c0.x,c0.y,c0.z,c0.w,c1.x,c1.y,c1.z,c1.w}};

    // sigmoid (precise: ids must be exact) + bias -> monotone keys, both tokens
    unsigned orig[2][8], s[2][8];
    #pragma unroll
    for (int i = 0; i < 8; i++) {
        float sa = 1.0f / (1.0f + expf(-xx[0][i]));
        float sb = 1.0f / (1.0f + expf(-xx[1][i]));
        orig[0][i] = f2key(sa + bb[i]); s[0][i] = orig[0][i];
        orig[1][i] = f2key(sb + bb[i]); s[1][i] = orig[1][i];
    }

    // per-lane descending sorts (independent -> interleaved by ptxas)
    SORT8(0)
    SORT8(1)

    // group score = top2 sum, per token
    unsigned m1[2] = {s[0][0], s[1][0]}, m2[2] = {s[0][1], s[1][1]};
    #pragma unroll
    for (int off = 1; off <= 2; off <<= 1) {
        #pragma unroll
        for (int k = 0; k < 2; k++) {
            unsigned o1 = __shfl_xor_sync(FULL, m1[k], off);
            unsigned o2 = __shfl_xor_sync(FULL, m2[k], off);
            unsigned l2 = umin(m1[k], o1);
            m1[k] = umax(m1[k], o1);
            m2[k] = umax(l2, umax(m2[k], o2));
        }
    }
    float gs[2] = {key2f(m1[0]) + key2f(m2[0]), key2f(m1[1]) + key2f(m2[1])};

    // broadcast group scores; rank own group (exact jax tie semantics)
    int grp = lane >> 2;
    int rank[2] = {0, 0};
    #pragma unroll
    for (int j = 0; j < 8; j++) {
        float gA = __shfl_sync(FULL, gs[0], j * 4);
        float gB = __shfl_sync(FULL, gs[1], j * 4);
        rank[0] += ((gA > gs[0]) || (gA == gs[0] && j < grp)) ? 1 : 0;
        rank[1] += ((gB > gs[1]) || (gB == gs[1] && j < grp)) ? 1 : 0;
    }
    #pragma unroll
    for (int k = 0; k < 2; k++) {
        bool sel = rank[k] < 4;
        #pragma unroll
        for (int i = 0; i < 8; i++) s[k][i] = sel ? s[k][i] : 0x80000000u;
    }

    // 8 extraction rounds, both tokens interleaved; brec init 1 keeps
    // the speculative bias gather in-bounds for lanes >= 8
    unsigned krec[2] = {0, 0}, brec[2] = {1, 1};
    #pragma unroll
    for (int r = 0; r < 8; r++) {
        unsigned kmA = __reduce_max_sync(FULL, s[0][0]);
        unsigned kmB = __reduce_max_sync(FULL, s[1][0]);
        bool eqA = (s[0][0] == kmA);
        bool eqB = (s[1][0] == kmB);
        unsigned balA = __ballot_sync(FULL, eqA);
        unsigned balB = __ballot_sync(FULL, eqB);
        if (lane == r) { krec[0] = kmA; brec[0] = balA; krec[1] = kmB; brec[1] = balB; }
        if (r < 7) {
            bool pA = eqA && ((balA & lmlt) == 0u);
            bool pB = eqB && ((balB & lmlt) == 0u);
            #pragma unroll
            for (int i = 0; i < 7; i++) {
                s[0][i] = pA ? s[0][i + 1] : s[0][i];
                s[1][i] = pB ? s[1][i + 1] : s[1][i];
            }
        }
    }
    int wrec[2] = {__ffs((int)brec[0]) - 1, __ffs((int)brec[1]) - 1};

    // index recovery, both tokens
    int gidx[2];
    #pragma unroll
    for (int k = 0; k < 2; k++) {
        unsigned gk[8];
        #pragma unroll
        for (int i = 0; i < 8; i++) gk[i] = __shfl_sync(FULL, orig[k][i], wrec[k]);
        int pos = 7;
        #pragma unroll
        for (int i = 6; i >= 0; i--) pos = (gk[i] == krec[k]) ? i : pos;
        gidx[k] = (wrec[k] << 3) + pos;
    }

    // weights: unbiased = biased - bias; octet normalize; scale
    float w[2], sum[2];
    #pragma unroll
    for (int k = 0; k < 2; k++) {
        w[k] = key2f(krec[k]) - __ldg(bias + gidx[k]);
        sum[k] = w[k];
    }
    #pragma unroll
    for (int off = 1; off <= 4; off <<= 1) {
        sum[0] += __shfl_xor_sync(FULL, sum[0], off);
        sum[1] += __shfl_xor_sync(FULL, sum[1], off);
    }

    if (lane < 8) {
        out[(size_t)tA * 8 + lane] = __fdividef(w[0], sum[0]) * 2.5f;
        out[(size_t)T * 8 + (size_t)tA * 8 + lane] = (float)gidx[0];
        if (hasB) {
            out[(size_t)(tA + 1) * 8 + lane] = __fdividef(w[1], sum[1]) * 2.5f;
            out[(size_t)T * 8 + (size_t)(tA + 1) * 8 + lane] = (float)gidx[1];
        }
    }
}

extern "C" void kernel_launch(void* const* d_in, const int* in_sizes, int n_in,
                              void* d_out, int out_size)
{
    // inputs: hidden_states (unused), router_logits [T,256], correction_bias [256]
    const float* logits = (const float*)d_in[1];
    const float* bias   = (const float*)d_in[2];
    float* out = (float*)d_out;

    int T = in_sizes[1] / 256;
    int blocks = (T + 7) / 8;              // 4 warps x 2 interleaved tokens
    topk_route_kernel<<<blocks, 128>>>(logits, bias, out, T);
}